// round 10
// baseline (speedup 1.0000x reference)
#include <cuda_runtime.h>

// Problem constants
#define BB 4
#define CC 8
#define TT 12
#define HH 256
#define WW 256

// Derived sizes (in float elements)
#define MK_ELEMS  (BB*CC*TT*HH*WW*2)      // 50331648  masked_kspace
#define OM_ELEMS  (BB*TT*HH*WW)           // 3145728   out_mask
#define FP_ELEMS  (BB*HH*WW)              // 262144    final_prob
#define MK4 (MK_ELEMS/4)                  // 12582912
#define OM4 (OM_ELEMS/4)                  // 786432
#define FP4 (FP_ELEMS/4)                  // 65536
#define TOT4 (MK4 + OM4 + FP4)            // 13434880  (divisible by 256 -> 52480 blocks)

// Scratch (allocation-free rule: __device__ globals)
__device__ float g_om[BB*TT*WW];   // out_mask 1d values (m + hard)
__device__ float g_fp[BB*WW];      // normed at t = T-1

// -------------------- Kernel A: policy (tiny, latency-optimized) --------------------
__global__ void policy_kernel(const float* __restrict__ mask,
                              const float* __restrict__ sampler,
                              const float* __restrict__ u) {
    const int bt   = blockIdx.x;        // 0..B*T-1
    const int b    = bt / TT;
    const int t    = bt - b * TT;
    const int w    = threadIdx.x;       // 0..255 == W
    const int lane = w & 31;
    const int wid  = w >> 5;            // 0..7

    __shared__ float smax[8];
    __shared__ float ssum[8];
    __shared__ float sbc[3];

    // m = mask[b,0,0,0,w,0] -> linear b*T*H*W + w
    const float m   = mask[(size_t)b * TT * HH * WW + w];
    const float fre = 1.0f - m;

    // softplus(SLOPE*s)/SLOPE, stable form
    const float x  = 10.0f * sampler[t * WW + w];
    const float sp = (fmaxf(x, 0.0f) + log1pf(expf(-fabsf(x)))) * 0.1f;

    // ---- fused reduction 1: max(fre*sp) and sum(fre) ----
    float vmax = fre * sp;
    float vsum = fre;
    #pragma unroll
    for (int o = 16; o > 0; o >>= 1) {
        vmax = fmaxf(vmax, __shfl_xor_sync(0xffffffffu, vmax, o));
        vsum += __shfl_xor_sync(0xffffffffu, vsum, o);
    }
    if (lane == 0) { smax[wid] = vmax; ssum[wid] = vsum; }
    __syncthreads();
    if (wid == 0) {
        float a = smax[lane & 7];
        float s = ssum[lane & 7];
        #pragma unroll
        for (int o = 4; o > 0; o >>= 1) {
            a = fmaxf(a, __shfl_xor_sync(0xffffffffu, a, o));
            s += __shfl_xor_sync(0xffffffffu, s, o);
        }
        if (lane == 0) { sbc[0] = a; sbc[1] = s; }
    }
    __syncthreads();
    const float denom  = sbc[0];
    const float n_free = sbc[1];

    const float prob = sp / denom;
    const float mp   = prob * fre;

    // ---- reduction 2: sum(masked_prob) ----
    float msum = mp;
    #pragma unroll
    for (int o = 16; o > 0; o >>= 1) {
        msum += __shfl_xor_sync(0xffffffffu, msum, o);
    }
    if (lane == 0) ssum[wid] = msum;
    __syncthreads();
    if (wid == 0) {
        float s = ssum[lane & 7];
        #pragma unroll
        for (int o = 4; o > 0; o >>= 1) {
            s += __shfl_xor_sync(0xffffffffu, s, o);
        }
        if (lane == 0) sbc[2] = s;
    }
    __syncthreads();
    const float mp_sum = sbc[2];

    const float xbar     = mp_sum / n_free;
    const float sparsity = 43.0f / n_free;
    const float r        = sparsity / xbar;
    const float beta     = (1.0f - sparsity) / (1.0f - xbar);

    float normed = (r <= 1.0f) ? (mp * r) : (1.0f - (1.0f - mp) * beta);
    normed *= fre;

    const float uu   = u[(size_t)(b * TT + t) * WW + w];
    const float hard = (normed > uu) ? 1.0f : 0.0f;

    g_om[bt * WW + w] = m + hard;
    if (t == TT - 1) g_fp[b * WW + w] = normed;
}

// -------------------- Kernel B: fused masked_kspace + out_mask bcast + final_prob --------------------
__global__ void fused_kernel(const float* __restrict__ kspace,
                             float* __restrict__ out) {
    const long long i4 = (long long)blockIdx.x * blockDim.x + threadIdx.x;

    if (i4 < MK4) {
        // masked_kspace: 128 float4 per (b,c,t,h) row (W*2 floats)
        const int wpair = (int)(i4 & 127);
        long long rest  = i4 >> 7;              // ((b*C+c)*T+t)*H + h
        rest >>= 8;                             // (b*C+c)*T + t    (H=256)
        const int t  = (int)(rest % TT);
        const int bc = (int)(rest / TT);
        const int b  = bc >> 3;                 // C=8

        const float4 k = __ldcs(reinterpret_cast<const float4*>(kspace) + i4);
        const int w0 = wpair * 2;
        const float* omrow = &g_om[(b * TT + t) * WW];
        const float om0 = __ldg(&omrow[w0]);
        const float om1 = __ldg(&omrow[w0 + 1]);

        float4 o;
        o.x = (om0 == 0.0f) ? 0.0f : om0 * k.x;
        o.y = (om0 == 0.0f) ? 0.0f : om0 * k.y;
        o.z = (om1 == 0.0f) ? 0.0f : om1 * k.z;
        o.w = (om1 == 0.0f) ? 0.0f : om1 * k.w;
        __stcs(reinterpret_cast<float4*>(out) + i4, o);
    } else if (i4 < MK4 + OM4) {
        // out_mask broadcast: layout (B,T,H,W), 64 float4 per (b,t,h) row
        const long long j = i4 - MK4;
        const int w4 = (int)(j & 63);
        long long rest = j >> 6;                // b*T*H + t*H + h
        rest >>= 8;                             // b*T + t
        const int t = (int)(rest % TT);
        const int b = (int)(rest / TT);
        const float4 v = *reinterpret_cast<const float4*>(&g_om[(b * TT + t) * WW + w4 * 4]);
        __stcs(reinterpret_cast<float4*>(out + MK_ELEMS) + j, v);
    } else {
        // final_prob: (B,H,W)
        const long long j = i4 - MK4 - OM4;     // < FP4 guaranteed (TOT4 % 256 == 0)
        const int w4 = (int)(j & 63);
        long long rest = j >> 6;                // b*H + h
        const int b = (int)(rest >> 8);
        const float4 v = *reinterpret_cast<const float4*>(&g_fp[b * WW + w4 * 4]);
        __stcs(reinterpret_cast<float4*>(out + MK_ELEMS + OM_ELEMS) + j, v);
    }
}

extern "C" void kernel_launch(void* const* d_in, const int* in_sizes, int n_in,
                              void* d_out, int out_size) {
    const float* mask    = (const float*)d_in[0];
    const float* kspace  = (const float*)d_in[1];
    const float* sampler = (const float*)d_in[2];
    const float* u       = (const float*)d_in[3];
    float* out = (float*)d_out;

    policy_kernel<<<BB * TT, WW>>>(mask, sampler, u);
    fused_kernel<<<TOT4 / 256, 256>>>(kspace, out);
}

// round 11
// speedup vs baseline: 1.1256x; 1.1256x over previous
#include <cuda_runtime.h>

// Problem constants
#define BB 4
#define CC 8
#define TT 12
#define HH 256
#define WW 256

// Derived sizes (in float elements)
#define MK_ELEMS  (BB*CC*TT*HH*WW*2)      // 50331648  masked_kspace
#define OM_ELEMS  (BB*TT*HH*WW)           // 3145728   out_mask
#define FP_ELEMS  (BB*HH*WW)              // 262144    final_prob
#define MK4 (MK_ELEMS/4)                  // 12582912
#define OM4 (OM_ELEMS/4)                  // 786432
#define FP4 (FP_ELEMS/4)                  // 65536
#define TOT4 (MK4 + OM4 + FP4)            // 13434880  (divisible by 256 -> 52480 blocks)

// Scratch (allocation-free rule: __device__ globals)
__device__ float g_om[BB*TT*WW];   // out_mask 1d values (m + hard)
__device__ float g_fp[BB*WW];      // normed at t = T-1

// -------------------- Kernel A: policy (tiny, latency-optimized) --------------------
__global__ void policy_kernel(const float* __restrict__ mask,
                              const float* __restrict__ sampler,
                              const float* __restrict__ u) {
    const int bt   = blockIdx.x;        // 0..B*T-1
    const int b    = bt / TT;
    const int t    = bt - b * TT;
    const int w    = threadIdx.x;       // 0..255 == W
    const int lane = w & 31;
    const int wid  = w >> 5;            // 0..7

    __shared__ float smax[8];
    __shared__ float ssum[8];
    __shared__ float sbc[3];

    // m = mask[b,0,0,0,w,0] -> linear b*T*H*W + w
    const float m   = mask[(size_t)b * TT * HH * WW + w];
    const float fre = 1.0f - m;

    // softplus(SLOPE*s)/SLOPE, stable form
    const float x  = 10.0f * sampler[t * WW + w];
    const float sp = (fmaxf(x, 0.0f) + log1pf(expf(-fabsf(x)))) * 0.1f;

    // ---- fused reduction 1: max(fre*sp) and sum(fre) ----
    float vmax = fre * sp;
    float vsum = fre;
    #pragma unroll
    for (int o = 16; o > 0; o >>= 1) {
        vmax = fmaxf(vmax, __shfl_xor_sync(0xffffffffu, vmax, o));
        vsum += __shfl_xor_sync(0xffffffffu, vsum, o);
    }
    if (lane == 0) { smax[wid] = vmax; ssum[wid] = vsum; }
    __syncthreads();
    if (wid == 0) {
        float a = smax[lane & 7];
        float s = ssum[lane & 7];
        #pragma unroll
        for (int o = 4; o > 0; o >>= 1) {
            a = fmaxf(a, __shfl_xor_sync(0xffffffffu, a, o));
            s += __shfl_xor_sync(0xffffffffu, s, o);
        }
        if (lane == 0) { sbc[0] = a; sbc[1] = s; }
    }
    __syncthreads();
    const float denom  = sbc[0];
    const float n_free = sbc[1];

    const float prob = sp / denom;
    const float mp   = prob * fre;

    // ---- reduction 2: sum(masked_prob) ----
    float msum = mp;
    #pragma unroll
    for (int o = 16; o > 0; o >>= 1) {
        msum += __shfl_xor_sync(0xffffffffu, msum, o);
    }
    if (lane == 0) ssum[wid] = msum;
    __syncthreads();
    if (wid == 0) {
        float s = ssum[lane & 7];
        #pragma unroll
        for (int o = 4; o > 0; o >>= 1) {
            s += __shfl_xor_sync(0xffffffffu, s, o);
        }
        if (lane == 0) sbc[2] = s;
    }
    __syncthreads();
    const float mp_sum = sbc[2];

    const float xbar     = mp_sum / n_free;
    const float sparsity = 43.0f / n_free;
    const float r        = sparsity / xbar;
    const float beta     = (1.0f - sparsity) / (1.0f - xbar);

    float normed = (r <= 1.0f) ? (mp * r) : (1.0f - (1.0f - mp) * beta);
    normed *= fre;

    const float uu   = u[(size_t)(b * TT + t) * WW + w];
    const float hard = (normed > uu) ? 1.0f : 0.0f;

    g_om[bt * WW + w] = m + hard;
    if (t == TT - 1) g_fp[b * WW + w] = normed;
}

// -------------------- Kernel B: fused masked_kspace + out_mask bcast + final_prob --------------------
__global__ void fused_kernel(const float* __restrict__ kspace,
                             float* __restrict__ out) {
    const long long i4 = (long long)blockIdx.x * blockDim.x + threadIdx.x;

    if (i4 < MK4) {
        // masked_kspace: 128 float4 per (b,c,t,h) row (W*2 floats)
        const int wpair = (int)(i4 & 127);
        long long rest  = i4 >> 7;              // ((b*C+c)*T+t)*H + h
        rest >>= 8;                             // (b*C+c)*T + t    (H=256)
        const int t  = (int)(rest % TT);
        const int bc = (int)(rest / TT);
        const int b  = bc >> 3;                 // C=8

        const float4 k = __ldcs(reinterpret_cast<const float4*>(kspace) + i4);
        const int w0 = wpair * 2;
        const float* omrow = &g_om[(b * TT + t) * WW];
        const float om0 = __ldg(&omrow[w0]);
        const float om1 = __ldg(&omrow[w0 + 1]);

        float4 o;
        o.x = (om0 == 0.0f) ? 0.0f : om0 * k.x;
        o.y = (om0 == 0.0f) ? 0.0f : om0 * k.y;
        o.z = (om1 == 0.0f) ? 0.0f : om1 * k.z;
        o.w = (om1 == 0.0f) ? 0.0f : om1 * k.w;
        __stcs(reinterpret_cast<float4*>(out) + i4, o);
    } else if (i4 < MK4 + OM4) {
        // out_mask broadcast: layout (B,T,H,W), 64 float4 per (b,t,h) row
        const long long j = i4 - MK4;
        const int w4 = (int)(j & 63);
        long long rest = j >> 6;                // b*T*H + t*H + h
        rest >>= 8;                             // b*T + t
        const int t = (int)(rest % TT);
        const int b = (int)(rest / TT);
        const float4 v = *reinterpret_cast<const float4*>(&g_om[(b * TT + t) * WW + w4 * 4]);
        __stcs(reinterpret_cast<float4*>(out + MK_ELEMS) + j, v);
    } else {
        // final_prob: (B,H,W)
        const long long j = i4 - MK4 - OM4;     // < FP4 guaranteed (TOT4 % 256 == 0)
        const int w4 = (int)(j & 63);
        long long rest = j >> 6;                // b*H + h
        const int b = (int)(rest >> 8);
        const float4 v = *reinterpret_cast<const float4*>(&g_fp[b * WW + w4 * 4]);
        __stcs(reinterpret_cast<float4*>(out + MK_ELEMS + OM_ELEMS) + j, v);
    }
}

extern "C" void kernel_launch(void* const* d_in, const int* in_sizes, int n_in,
                              void* d_out, int out_size) {
    const float* mask    = (const float*)d_in[0];
    const float* kspace  = (const float*)d_in[1];
    const float* sampler = (const float*)d_in[2];
    const float* u       = (const float*)d_in[3];
    float* out = (float*)d_out;

    policy_kernel<<<BB * TT, WW>>>(mask, sampler, u);
    fused_kernel<<<TOT4 / 256, 256>>>(kspace, out);
}

// round 12
// speedup vs baseline: 1.1299x; 1.0038x over previous
#include <cuda_runtime.h>

// Problem constants
#define BB 4
#define CC 8
#define TT 12
#define HH 256
#define WW 256

// Derived sizes (in float elements)
#define MK_ELEMS  (BB*CC*TT*HH*WW*2)      // 50331648  masked_kspace
#define OM_ELEMS  (BB*TT*HH*WW)           // 3145728   out_mask
#define FP_ELEMS  (BB*HH*WW)              // 262144    final_prob
#define MK4 (MK_ELEMS/4)                  // 12582912
#define OM4 (OM_ELEMS/4)                  // 786432
#define FP4 (FP_ELEMS/4)                  // 65536
#define TOT4 (MK4 + OM4 + FP4)            // 13434880  (divisible by 256 -> 52480 blocks)

// Scratch (allocation-free rule: __device__ globals)
__device__ float g_om[BB*TT*WW];   // out_mask 1d values (m + hard)
__device__ float g_fp[BB*WW];      // normed at t = T-1

// -------------------- Kernel A: policy (tiny, latency-optimized) --------------------
__global__ void policy_kernel(const float* __restrict__ mask,
                              const float* __restrict__ sampler,
                              const float* __restrict__ u) {
    const int bt   = blockIdx.x;        // 0..B*T-1
    const int b    = bt / TT;
    const int t    = bt - b * TT;
    const int w    = threadIdx.x;       // 0..255 == W
    const int lane = w & 31;
    const int wid  = w >> 5;            // 0..7

    __shared__ float smax[8];
    __shared__ float ssum[8];
    __shared__ float sbc[3];

    // m = mask[b,0,0,0,w,0] -> linear b*T*H*W + w
    const float m   = mask[(size_t)b * TT * HH * WW + w];
    const float fre = 1.0f - m;

    // softplus(SLOPE*s)/SLOPE, stable form
    const float x  = 10.0f * sampler[t * WW + w];
    const float sp = (fmaxf(x, 0.0f) + log1pf(expf(-fabsf(x)))) * 0.1f;

    // ---- fused reduction 1: max(fre*sp) and sum(fre) ----
    float vmax = fre * sp;
    float vsum = fre;
    #pragma unroll
    for (int o = 16; o > 0; o >>= 1) {
        vmax = fmaxf(vmax, __shfl_xor_sync(0xffffffffu, vmax, o));
        vsum += __shfl_xor_sync(0xffffffffu, vsum, o);
    }
    if (lane == 0) { smax[wid] = vmax; ssum[wid] = vsum; }
    __syncthreads();
    if (wid == 0) {
        float a = smax[lane & 7];
        float s = ssum[lane & 7];
        #pragma unroll
        for (int o = 4; o > 0; o >>= 1) {
            a = fmaxf(a, __shfl_xor_sync(0xffffffffu, a, o));
            s += __shfl_xor_sync(0xffffffffu, s, o);
        }
        if (lane == 0) { sbc[0] = a; sbc[1] = s; }
    }
    __syncthreads();
    const float denom  = sbc[0];
    const float n_free = sbc[1];

    const float prob = sp / denom;
    const float mp   = prob * fre;

    // ---- reduction 2: sum(masked_prob) ----
    float msum = mp;
    #pragma unroll
    for (int o = 16; o > 0; o >>= 1) {
        msum += __shfl_xor_sync(0xffffffffu, msum, o);
    }
    if (lane == 0) ssum[wid] = msum;
    __syncthreads();
    if (wid == 0) {
        float s = ssum[lane & 7];
        #pragma unroll
        for (int o = 4; o > 0; o >>= 1) {
            s += __shfl_xor_sync(0xffffffffu, s, o);
        }
        if (lane == 0) sbc[2] = s;
    }
    __syncthreads();
    const float mp_sum = sbc[2];

    const float xbar     = mp_sum / n_free;
    const float sparsity = 43.0f / n_free;
    const float r        = sparsity / xbar;
    const float beta     = (1.0f - sparsity) / (1.0f - xbar);

    float normed = (r <= 1.0f) ? (mp * r) : (1.0f - (1.0f - mp) * beta);
    normed *= fre;

    const float uu   = u[(size_t)(b * TT + t) * WW + w];
    const float hard = (normed > uu) ? 1.0f : 0.0f;

    g_om[bt * WW + w] = m + hard;
    if (t == TT - 1) g_fp[b * WW + w] = normed;
}

// -------------------- Kernel B: fused masked_kspace + out_mask bcast + final_prob --------------------
__global__ void fused_kernel(const float* __restrict__ kspace,
                             float* __restrict__ out) {
    const long long i4 = (long long)blockIdx.x * blockDim.x + threadIdx.x;

    if (i4 < MK4) {
        // masked_kspace: 128 float4 per (b,c,t,h) row (W*2 floats)
        const int wpair = (int)(i4 & 127);
        long long rest  = i4 >> 7;              // ((b*C+c)*T+t)*H + h
        rest >>= 8;                             // (b*C+c)*T + t    (H=256)
        const int t  = (int)(rest % TT);
        const int bc = (int)(rest / TT);
        const int b  = bc >> 3;                 // C=8

        const float4 k = __ldcs(reinterpret_cast<const float4*>(kspace) + i4);
        const int w0 = wpair * 2;
        const float* omrow = &g_om[(b * TT + t) * WW];
        const float om0 = __ldg(&omrow[w0]);
        const float om1 = __ldg(&omrow[w0 + 1]);

        float4 o;
        o.x = (om0 == 0.0f) ? 0.0f : om0 * k.x;
        o.y = (om0 == 0.0f) ? 0.0f : om0 * k.y;
        o.z = (om1 == 0.0f) ? 0.0f : om1 * k.z;
        o.w = (om1 == 0.0f) ? 0.0f : om1 * k.w;
        __stcs(reinterpret_cast<float4*>(out) + i4, o);
    } else if (i4 < MK4 + OM4) {
        // out_mask broadcast: layout (B,T,H,W), 64 float4 per (b,t,h) row
        const long long j = i4 - MK4;
        const int w4 = (int)(j & 63);
        long long rest = j >> 6;                // b*T*H + t*H + h
        rest >>= 8;                             // b*T + t
        const int t = (int)(rest % TT);
        const int b = (int)(rest / TT);
        const float4 v = *reinterpret_cast<const float4*>(&g_om[(b * TT + t) * WW + w4 * 4]);
        __stcs(reinterpret_cast<float4*>(out + MK_ELEMS) + j, v);
    } else {
        // final_prob: (B,H,W)
        const long long j = i4 - MK4 - OM4;     // < FP4 guaranteed (TOT4 % 256 == 0)
        const int w4 = (int)(j & 63);
        long long rest = j >> 6;                // b*H + h
        const int b = (int)(rest >> 8);
        const float4 v = *reinterpret_cast<const float4*>(&g_fp[b * WW + w4 * 4]);
        __stcs(reinterpret_cast<float4*>(out + MK_ELEMS + OM_ELEMS) + j, v);
    }
}

extern "C" void kernel_launch(void* const* d_in, const int* in_sizes, int n_in,
                              void* d_out, int out_size) {
    const float* mask    = (const float*)d_in[0];
    const float* kspace  = (const float*)d_in[1];
    const float* sampler = (const float*)d_in[2];
    const float* u       = (const float*)d_in[3];
    float* out = (float*)d_out;

    policy_kernel<<<BB * TT, WW>>>(mask, sampler, u);
    fused_kernel<<<TOT4 / 256, 256>>>(kspace, out);
}